// round 14
// baseline (speedup 1.0000x reference)
#include <cuda_runtime.h>
#include <math.h>

#define BATCH 64
#define NPRED 16384
#define NGT   8192
#define NBOX  (BATCH * NGT)
#define NSM   148
#define CPS   6
#define GRID  (NSM * CPS)       // 888: one full wave
#define TPB   256
#define NWARP (TPB / 32)        // 8
#define CSTR  25                // corner smem stride (odd -> conflict-free)
#define PSTR  9                 // pred smem stride (odd -> conflict-free)

__device__ float g_part[GRID][3];
__device__ int   g_count = 0;

__device__ __forceinline__ float warp_redf(float v) {
#pragma unroll
    for (int o = 16; o > 0; o >>= 1) v += __shfl_down_sync(0xffffffffu, v, o);
    return v;
}

__device__ __forceinline__ double warp_redd(double v) {
#pragma unroll
    for (int o = 16; o > 0; o >>= 1) v += __shfl_down_sync(0xffffffffu, v, o);
    return v;
}

__device__ __forceinline__ float sl1(float a, float b) {
    float d = fabsf(a - b);
    return d < 1.0f ? 0.5f * d * d : d - 0.5f;
}

__device__ __forceinline__ float fsqrt_fast(float x) {
    x = fmaxf(x, 1e-30f);
    return x * rsqrtf(x);
}

// acos(r), r in [-1,1], abs err ~7e-5 (Hastings 4-term)
__device__ __forceinline__ float facos(float r) {
    float a  = fabsf(r);
    float t  = fsqrt_fast(1.0f - a);
    float p  = fmaf(a, fmaf(a, fmaf(a, -0.0187293f, 0.0742610f), -0.2121144f), 1.5707288f);
    float ac = t * p;
    return (r < 0.0f) ? (3.14159265358979f - ac) : ac;
}

// atan2(y,x), abs err ~1e-6
__device__ __forceinline__ float fatan2(float y, float x) {
    float ax = fabsf(x), ay = fabsf(y);
    float mn = fminf(ax, ay), mx = fmaxf(ax, ay);
    float a  = __fdividef(mn, mx);
    float s  = a * a;
    float r  = fmaf(s, fmaf(s, fmaf(s, fmaf(s, fmaf(s, -0.0117212f, 0.05265332f),
                 -0.11643287f), 0.19354346f), -0.33262347f), 0.99997726f) * a;
    if (ay > ax) r = 1.57079632679f - r;
    if (x < 0.0f) r = 3.14159265359f - r;
    return copysignf(r, y);
}

__global__ void __launch_bounds__(TPB, CPS) main_k(
    const float* __restrict__ pred_boxes,
    const float* __restrict__ pred_scores,
    const float* __restrict__ gt_corners,
    float* __restrict__ out)
{
    __shared__ float s_cor[NWARP][32 * CSTR];   // 8 * 800 * 4B = 25.6 KB
    __shared__ float s_prd[NWARP][32 * PSTR];   // 8 * 288 * 4B =  9.2 KB

    const int lane  = threadIdx.x & 31;
    const int wrp   = threadIdx.x >> 5;
    const int gw    = blockIdx.x * NWARP + wrp;     // global warp id
    const int nwrp  = GRID * NWARP;                 // 7104
    float* sc = s_cor[wrp];
    float* sp = s_prd[wrp];

    float reg = 0.f, lg = 0.f, sq = 0.f;

    // ---- GT boxes: warp-tile of 32 consecutive boxes per iteration ----
    for (int base = gw * 32; base < NBOX; base += nwrp * 32) {
        // stage corners: 32 boxes * 96B = 3KB, 6 coalesced float4 loads/lane
        const float4* csrc = reinterpret_cast<const float4*>(gt_corners + (size_t)base * 24);
#pragma unroll
        for (int r = 0; r < 6; r++) {
            float4 v = csrc[r * 32 + lane];
            int q  = r * 32 + lane;        // quad index (4 floats, never crosses box)
            int bx = q / 6;                // box within tile
            int k  = (q - bx * 6) * 4;     // float offset within box
            float* d = &sc[bx * CSTR + k];
            d[0] = v.x; d[1] = v.y; d[2] = v.z; d[3] = v.w;
        }

        // stage preds: 32 boxes * 7 floats = 224 floats = 56 float4 (16B-aligned)
        int bb = base >> 13;
        int mm = base & (NGT - 1);
        const float4* psrc = reinterpret_cast<const float4*>(
            pred_boxes + ((size_t)bb * NPRED + mm) * 7);
        {
            float4 v = psrc[lane];
#pragma unroll
            for (int c = 0; c < 4; c++) {
                int g  = lane * 4 + c;
                int bx = g / 7;
                sp[bx * PSTR + (g - bx * 7)] = (&v.x)[c];
            }
            if (lane < 24) {
                float4 w = psrc[32 + lane];
#pragma unroll
                for (int c = 0; c < 4; c++) {
                    int g  = 128 + lane * 4 + c;
                    int bx = g / 7;
                    sp[bx * PSTR + (g - bx * 7)] = (&w.x)[c];
                }
            }
        }
        __syncwarp();

        // compute: this lane's box from conflict-free smem
        const float* c = &sc[lane * CSTR];
        float x0=c[0], y0=c[1], z0=c[2],  x1=c[3],  y1=c[4],  z1=c[5];
        float x2=c[6], y2=c[7], z2=c[8],  x3=c[9],  y3=c[10], z3=c[11];
        float x4=c[12],y4=c[13],z4=c[14], x5=c[15], y5=c[16], z5=c[17];
        float x6=c[18],y6=c[19],z6=c[20], x7=c[21], y7=c[22], z7=c[23];

        // raw moments; cov = S2 - S1*(S1/8)
        float sx=0.f, sy=0.f, sz=0.f;
        float sxx=0.f, sxy=0.f, sxz=0.f, syy=0.f, syz=0.f, szz=0.f;
#define ACC(X,Y,Z) { sx += (X); sy += (Y); sz += (Z); \
        sxx = fmaf((X),(X),sxx); sxy = fmaf((X),(Y),sxy); sxz = fmaf((X),(Z),sxz); \
        syy = fmaf((Y),(Y),syy); syz = fmaf((Y),(Z),syz); szz = fmaf((Z),(Z),szz); }
        ACC(x0,y0,z0) ACC(x1,y1,z1) ACC(x2,y2,z2) ACC(x3,y3,z3)
        ACC(x4,y4,z4) ACC(x5,y5,z5) ACC(x6,y6,z6) ACC(x7,y7,z7)
#undef ACC
        float mx = sx * 0.125f, my = sy * 0.125f, mz = sz * 0.125f;
        float axx = fmaf(-sx, mx, sxx), axy = fmaf(-sx, my, sxy);
        float axz = fmaf(-sx, mz, sxz), ayy = fmaf(-sy, my, syy);
        float ayz = fmaf(-sy, mz, syz), azz = fmaf(-sz, mz, szz);

        float qv = (axx + ayy + azz) * (1.f/3.f);
        float pp1 = axy*axy + axz*axz + ayz*ayz;
        float a0 = axx - qv, a1 = ayy - qv, a2 = azz - qv;
        float p2 = a0*a0 + a1*a1 + a2*a2 + 2.f*pp1;
        float p  = fsqrt_fast(p2 * (1.f/6.f));
        float ip = __frcp_rn(p);
        float b00=a0*ip, b11=a1*ip, b22=a2*ip;
        float b01=axy*ip, b02=axz*ip, b12=ayz*ip;
        float detb = b00*(b11*b22 - b12*b12)
                   - b01*(b01*b22 - b12*b02)
                   + b02*(b01*b12 - b11*b02);
        float r   = fminf(fmaxf(0.5f*detb, -1.f), 1.f);
        float phi = facos(r) * (1.f/3.f);
        float lam2 = qv + 2.f*p*__cosf(phi);
        float lam0 = qv + 2.f*p*__cosf(phi + 2.0943951023931953f);
        float lam1 = 3.f*qv - lam0 - lam2;

        float s0 = 2.f*fsqrt_fast(fmaxf(lam1, 0.f));
        float s1 = 2.f*fsqrt_fast(fmaxf(lam2, 0.f));
        float s2 = 2.f*fsqrt_fast(fmaxf(lam0, 0.f));

        float m00 = axx - lam0, m11 = ayy - lam0, m22 = azz - lam0;
        float c0x = axy*ayz - axz*m11, c0y = axz*axy - m00*ayz;
        float c0z = m00*m11 - axy*axy;
        float c1x = axy*m22 - axz*ayz, c1y = axz*axz - m00*m22;
        float c1z = m00*ayz - axy*axz;
        float c2x = m11*m22 - ayz*ayz, c2y = ayz*axz - axy*m22;
        float c2z = axy*ayz - m11*axz;
        float n0 = c0x*c0x + c0y*c0y + c0z*c0z;
        float n1 = c1x*c1x + c1y*c1y + c1z*c1z;
        float n2 = c2x*c2x + c2y*c2y + c2z*c2z;
        float vx = c0x, vy = c0y, nb = n0;
        if (n1 > nb) { vx = c1x; vy = c1y; nb = n1; }
        if (n2 > nb) { vx = c2x; vy = c2y; }
        float yaw = fatan2(vy, vx);

        const float* pq = &sp[lane * PSTR];
        reg += sl1(pq[0], mx) + sl1(pq[1], my) + sl1(pq[2], mz)
             + sl1(pq[3], s0) + sl1(pq[4], s1) + sl1(pq[5], s2)
             + sl1(pq[6], yaw);

        __syncwarp();   // WAR: all lanes done reading before next restage
    }

    // ---- scores (already coalesced) ----
    {
        const int NS4 = (BATCH * NPRED) / 4;
        const int tid = blockIdx.x * TPB + threadIdx.x;
        const int nth = GRID * TPB;
        const float4* spv = reinterpret_cast<const float4*>(pred_scores);
        for (int j = tid; j < NS4; j += nth) {
            float4 s = spv[j];
            int n = (j * 4) & (NPRED - 1);
            if (n < NGT) {
                lg += __logf(fminf(fmaxf(s.x, 1e-12f), 1.f))
                    + __logf(fminf(fmaxf(s.y, 1e-12f), 1.f))
                    + __logf(fminf(fmaxf(s.z, 1e-12f), 1.f))
                    + __logf(fminf(fmaxf(s.w, 1e-12f), 1.f));
            } else {
                sq += s.x*s.x + s.y*s.y + s.z*s.z + s.w*s.w;
            }
        }
    }

    // ---- block reduction -> per-block float partials ----
    __shared__ float shf[3][NWARP];
    reg = warp_redf(reg); lg = warp_redf(lg); sq = warp_redf(sq);
    if (lane == 0) { shf[0][wrp] = reg; shf[1][wrp] = lg; shf[2][wrp] = sq; }
    __syncthreads();
    if (wrp == 0) {
        float a = (lane < NWARP) ? shf[0][lane] : 0.f;
        float b = (lane < NWARP) ? shf[1][lane] : 0.f;
        float c = (lane < NWARP) ? shf[2][lane] : 0.f;
        a = warp_redf(a); b = warp_redf(b); c = warp_redf(c);
        if (lane == 0) {
            g_part[blockIdx.x][0] = a;
            g_part[blockIdx.x][1] = b;
            g_part[blockIdx.x][2] = c;
        }
    }

    // ---- last-block final reduction (double, runs once) ----
    __shared__ bool amLast;
    __threadfence();
    if (threadIdx.x == 0)
        amLast = (atomicAdd(&g_count, 1) == GRID - 1);
    __syncthreads();

    if (amLast) {
        double a = 0.0, b = 0.0, c = 0.0;
        for (int k = threadIdx.x; k < GRID; k += TPB) {
            a += (double)g_part[k][0];
            b += (double)g_part[k][1];
            c += (double)g_part[k][2];
        }
        a = warp_redd(a); b = warp_redd(b); c = warp_redd(c);
        __shared__ double shd[3][NWARP];
        if (lane == 0) { shd[0][wrp] = a; shd[1][wrp] = b; shd[2][wrp] = c; }
        __syncthreads();
        if (wrp == 0) {
            double ra = (lane < NWARP) ? shd[0][lane] : 0.0;
            double rb = (lane < NWARP) ? shd[1][lane] : 0.0;
            double rc = (lane < NWARP) ? shd[2][lane] : 0.0;
            ra = warp_redd(ra); rb = warp_redd(rb); rc = warp_redd(rc);
            if (lane == 0) {
                double regm  = ra / (double)((long long)BATCH * NGT * 7);
                double bce   = -rb / (double)((long long)BATCH * NGT);
                double extra = 0.3 * rc / (double)BATCH;
                out[0] = (float)(regm + bce + extra);
                g_count = 0;
            }
        }
    }
}

extern "C" void kernel_launch(void* const* d_in, const int* in_sizes, int n_in,
                              void* d_out, int out_size) {
    const float* pred_boxes  = (const float*)d_in[0];
    const float* pred_scores = (const float*)d_in[1];
    const float* gt_corners  = (const float*)d_in[2];

    main_k<<<GRID, TPB>>>(pred_boxes, pred_scores, gt_corners, (float*)d_out);
}

// round 16
// speedup vs baseline: 1.2593x; 1.2593x over previous
#include <cuda_runtime.h>
#include <math.h>

#define BATCH 64
#define NPRED 16384
#define NGT   8192
#define NBOX  (BATCH * NGT)
#define NSM   148
#define CPS   7
#define GRID  (NSM * CPS)       // 1036: one full wave at 7 CTAs/SM
#define TPB   256

__device__ float g_part[GRID][3];
__device__ int   g_count = 0;

__device__ __forceinline__ float warp_redf(float v) {
#pragma unroll
    for (int o = 16; o > 0; o >>= 1) v += __shfl_down_sync(0xffffffffu, v, o);
    return v;
}

__device__ __forceinline__ double warp_redd(double v) {
#pragma unroll
    for (int o = 16; o > 0; o >>= 1) v += __shfl_down_sync(0xffffffffu, v, o);
    return v;
}

__device__ __forceinline__ float sl1(float a, float b) {
    float d = fabsf(a - b);
    return d < 1.0f ? 0.5f * d * d : d - 0.5f;
}

__device__ __forceinline__ float fsqrt_fast(float x) {
    x = fmaxf(x, 1e-30f);
    return x * rsqrtf(x);
}

// acos(r), r in [-1,1], abs err ~7e-5 (Hastings 4-term)
__device__ __forceinline__ float facos(float r) {
    float a  = fabsf(r);
    float t  = fsqrt_fast(1.0f - a);
    float p  = fmaf(a, fmaf(a, fmaf(a, -0.0187293f, 0.0742610f), -0.2121144f), 1.5707288f);
    float ac = t * p;
    return (r < 0.0f) ? (3.14159265358979f - ac) : ac;
}

// atan2(y,x), abs err ~1e-6
__device__ __forceinline__ float fatan2(float y, float x) {
    float ax = fabsf(x), ay = fabsf(y);
    float mn = fminf(ax, ay), mx = fmaxf(ax, ay);
    float a  = __fdividef(mn, mx);
    float s  = a * a;
    float r  = fmaf(s, fmaf(s, fmaf(s, fmaf(s, fmaf(s, -0.0117212f, 0.05265332f),
                 -0.11643287f), 0.19354346f), -0.33262347f), 0.99997726f) * a;
    if (ay > ax) r = 1.57079632679f - r;
    if (x < 0.0f) r = 3.14159265359f - r;
    return copysignf(r, y);
}

__global__ void __launch_bounds__(TPB, CPS) main_k(
    const float* __restrict__ pred_boxes,
    const float* __restrict__ pred_scores,
    const float* __restrict__ gt_corners,
    float* __restrict__ out)
{
    const int tid = blockIdx.x * TPB + threadIdx.x;
    const int nth = GRID * TPB;

    float reg = 0.f, lg = 0.f, sq = 0.f;

    // ---- GT boxes ----
    for (int i = tid; i < NBOX; i += nth) {
        const float4* cp = reinterpret_cast<const float4*>(gt_corners) + (size_t)i * 6;
        float4 q0 = cp[0], q1 = cp[1], q2 = cp[2], q3 = cp[3], q4 = cp[4], q5 = cp[5];

        int b = i >> 13;
        int m = i & (NGT - 1);
        const float* pp = pred_boxes + ((size_t)b * NPRED + m) * 7;
        float p0 = pp[0], p1v = pp[1], p2v = pp[2], p3 = pp[3];
        float p4 = pp[4], p5 = pp[5], p6 = pp[6];

        float x0=q0.x,y0=q0.y,z0=q0.z,  x1=q0.w,y1=q1.x,z1=q1.y;
        float x2=q1.z,y2=q1.w,z2=q2.x,  x3=q2.y,y3=q2.z,z3=q2.w;
        float x4=q3.x,y4=q3.y,z4=q3.z,  x5=q3.w,y5=q4.x,z5=q4.y;
        float x6=q4.z,y6=q4.w,z6=q5.x,  x7=q5.y,y7=q5.z,z7=q5.w;

        // raw moments; cov = S2 - S1*(S1/8)
        float sx=0.f, sy=0.f, sz=0.f;
        float sxx=0.f, sxy=0.f, sxz=0.f, syy=0.f, syz=0.f, szz=0.f;
#define ACC(X,Y,Z) { sx += (X); sy += (Y); sz += (Z); \
        sxx = fmaf((X),(X),sxx); sxy = fmaf((X),(Y),sxy); sxz = fmaf((X),(Z),sxz); \
        syy = fmaf((Y),(Y),syy); syz = fmaf((Y),(Z),syz); szz = fmaf((Z),(Z),szz); }
        ACC(x0,y0,z0) ACC(x1,y1,z1) ACC(x2,y2,z2) ACC(x3,y3,z3)
        ACC(x4,y4,z4) ACC(x5,y5,z5) ACC(x6,y6,z6) ACC(x7,y7,z7)
#undef ACC
        float mx = sx * 0.125f, my = sy * 0.125f, mz = sz * 0.125f;
        float axx = fmaf(-sx, mx, sxx), axy = fmaf(-sx, my, sxy);
        float axz = fmaf(-sx, mz, sxz), ayy = fmaf(-sy, my, syy);
        float ayz = fmaf(-sy, mz, syz), azz = fmaf(-sz, mz, szz);

        float qv = (axx + ayy + azz) * (1.f/3.f);
        float pp1 = axy*axy + axz*axz + ayz*ayz;
        float a0 = axx - qv, a1 = ayy - qv, a2 = azz - qv;
        float p2 = fmaxf((a0*a0 + a1*a1 + a2*a2 + 2.f*pp1) * (1.f/6.f), 1e-30f);
        float ip_ = rsqrtf(p2);      // shared: p = p2*ip_, 1/p = ip_
        float p  = p2 * ip_;
        float ip = ip_;
        float b00=a0*ip, b11=a1*ip, b22=a2*ip;
        float b01=axy*ip, b02=axz*ip, b12=ayz*ip;
        float detb = b00*(b11*b22 - b12*b12)
                   - b01*(b01*b22 - b12*b02)
                   + b02*(b01*b12 - b11*b02);
        float r   = fminf(fmaxf(0.5f*detb, -1.f), 1.f);
        float phi = facos(r) * (1.f/3.f);
        float sph, cph;
        __sincosf(phi, &sph, &cph);
        // cos(phi + 2*pi/3) = -0.5*c - (sqrt(3)/2)*s
        float c2  = fmaf(-0.5f, cph, -0.86602540378f * sph);
        float lam2 = qv + 2.f*p*cph;                    // largest
        float lam0 = qv + 2.f*p*c2;                     // smallest
        float lam1 = 3.f*qv - lam0 - lam2;

        float s0 = 2.f*fsqrt_fast(fmaxf(lam1, 0.f));
        float s1 = 2.f*fsqrt_fast(fmaxf(lam2, 0.f));
        float s2 = 2.f*fsqrt_fast(fmaxf(lam0, 0.f));

        float m00 = axx - lam0, m11 = ayy - lam0, m22 = azz - lam0;
        float c0x = axy*ayz - axz*m11, c0y = axz*axy - m00*ayz;
        float c0z = m00*m11 - axy*axy;
        float c1x = axy*m22 - axz*ayz, c1y = axz*axz - m00*m22;
        float c1z = m00*ayz - axy*axz;
        float c2x = m11*m22 - ayz*ayz, c2y = ayz*axz - axy*m22;
        float c2z = axy*ayz - m11*axz;
        float n0 = c0x*c0x + c0y*c0y + c0z*c0z;
        float n1 = c1x*c1x + c1y*c1y + c1z*c1z;
        float n2 = c2x*c2x + c2y*c2y + c2z*c2z;
        float vx = c0x, vy = c0y, nb = n0;
        if (n1 > nb) { vx = c1x; vy = c1y; nb = n1; }
        if (n2 > nb) { vx = c2x; vy = c2y; }
        float yaw = fatan2(vy, vx);

        reg += sl1(p0, mx) + sl1(p1v, my) + sl1(p2v, mz)
             + sl1(p3, s0) + sl1(p4, s1) + sl1(p5, s2)
             + sl1(p6, yaw);
    }

    // ---- scores: log-pairing halves the __logf count ----
    {
        const int NS4 = (BATCH * NPRED) / 4;
        const float4* spv = reinterpret_cast<const float4*>(pred_scores);
        for (int j = tid; j < NS4; j += nth) {
            float4 s = spv[j];
            int n = (j * 4) & (NPRED - 1);
            if (n < NGT) {
                float cx = fminf(fmaxf(s.x, 1e-12f), 1.f);
                float cy = fminf(fmaxf(s.y, 1e-12f), 1.f);
                float cz = fminf(fmaxf(s.z, 1e-12f), 1.f);
                float cw = fminf(fmaxf(s.w, 1e-12f), 1.f);
                lg += __logf(cx * cy) + __logf(cz * cw);
            } else {
                sq += s.x*s.x + s.y*s.y + s.z*s.z + s.w*s.w;
            }
        }
    }

    // ---- block reduction -> per-block float partials ----
    __shared__ float shf[3][8];
    int lane = threadIdx.x & 31, wid = threadIdx.x >> 5;
    reg = warp_redf(reg); lg = warp_redf(lg); sq = warp_redf(sq);
    if (lane == 0) { shf[0][wid] = reg; shf[1][wid] = lg; shf[2][wid] = sq; }
    __syncthreads();
    if (wid == 0) {
        float a = (lane < 8) ? shf[0][lane] : 0.f;
        float b = (lane < 8) ? shf[1][lane] : 0.f;
        float c = (lane < 8) ? shf[2][lane] : 0.f;
        a = warp_redf(a); b = warp_redf(b); c = warp_redf(c);
        if (lane == 0) {
            g_part[blockIdx.x][0] = a;
            g_part[blockIdx.x][1] = b;
            g_part[blockIdx.x][2] = c;
        }
    }

    // ---- last-block final reduction (double, runs once) ----
    __shared__ bool amLast;
    __threadfence();
    if (threadIdx.x == 0)
        amLast = (atomicAdd(&g_count, 1) == GRID - 1);
    __syncthreads();

    if (amLast) {
        double a = 0.0, b = 0.0, c = 0.0;
        for (int k = threadIdx.x; k < GRID; k += TPB) {
            a += (double)g_part[k][0];
            b += (double)g_part[k][1];
            c += (double)g_part[k][2];
        }
        a = warp_redd(a); b = warp_redd(b); c = warp_redd(c);
        __shared__ double shd[3][8];
        if (lane == 0) { shd[0][wid] = a; shd[1][wid] = b; shd[2][wid] = c; }
        __syncthreads();
        if (wid == 0) {
            double ra = (lane < 8) ? shd[0][lane] : 0.0;
            double rb = (lane < 8) ? shd[1][lane] : 0.0;
            double rc = (lane < 8) ? shd[2][lane] : 0.0;
            ra = warp_redd(ra); rb = warp_redd(rb); rc = warp_redd(rc);
            if (lane == 0) {
                double regm  = ra / (double)((long long)BATCH * NGT * 7);
                double bce   = -rb / (double)((long long)BATCH * NGT);
                double extra = 0.3 * rc / (double)BATCH;
                out[0] = (float)(regm + bce + extra);
                g_count = 0;
            }
        }
    }
}

extern "C" void kernel_launch(void* const* d_in, const int* in_sizes, int n_in,
                              void* d_out, int out_size) {
    const float* pred_boxes  = (const float*)d_in[0];
    const float* pred_scores = (const float*)d_in[1];
    const float* gt_corners  = (const float*)d_in[2];

    main_k<<<GRID, TPB>>>(pred_boxes, pred_scores, gt_corners, (float*)d_out);
}

// round 17
// speedup vs baseline: 1.2642x; 1.0039x over previous
#include <cuda_runtime.h>
#include <math.h>

#define BATCH 64
#define NPRED 16384
#define NGT   8192
#define NBOX  (BATCH * NGT)
#define NSM   148
#define CPS   7
#define GRID  (NSM * CPS)       // 1036
#define TPB   256
#define NTH   (GRID * TPB)      // 265216
#define NS4   ((BATCH * NPRED) / 4)   // 262144

__device__ float g_part[GRID][3];
__device__ int   g_count = 0;

__device__ __forceinline__ float warp_redf(float v) {
#pragma unroll
    for (int o = 16; o > 0; o >>= 1) v += __shfl_down_sync(0xffffffffu, v, o);
    return v;
}

__device__ __forceinline__ double warp_redd(double v) {
#pragma unroll
    for (int o = 16; o > 0; o >>= 1) v += __shfl_down_sync(0xffffffffu, v, o);
    return v;
}

__device__ __forceinline__ float sl1(float a, float b) {
    float d = fabsf(a - b);
    return d < 1.0f ? 0.5f * d * d : d - 0.5f;
}

__device__ __forceinline__ float fsqrt_fast(float x) {
    x = fmaxf(x, 1e-30f);
    return x * rsqrtf(x);
}

// acos(r), r in [-1,1], abs err ~7e-5 (Hastings 4-term)
__device__ __forceinline__ float facos(float r) {
    float a  = fabsf(r);
    float t  = fsqrt_fast(1.0f - a);
    float p  = fmaf(a, fmaf(a, fmaf(a, -0.0187293f, 0.0742610f), -0.2121144f), 1.5707288f);
    float ac = t * p;
    return (r < 0.0f) ? (3.14159265358979f - ac) : ac;
}

// atan2(y,x), abs err ~1e-6
__device__ __forceinline__ float fatan2(float y, float x) {
    float ax = fabsf(x), ay = fabsf(y);
    float mn = fminf(ax, ay), mx = fmaxf(ax, ay);
    float a  = __fdividef(mn, mx);
    float s  = a * a;
    float r  = fmaf(s, fmaf(s, fmaf(s, fmaf(s, fmaf(s, -0.0117212f, 0.05265332f),
                 -0.11643287f), 0.19354346f), -0.33262347f), 0.99997726f) * a;
    if (ay > ax) r = 1.57079632679f - r;
    if (x < 0.0f) r = 3.14159265359f - r;
    return copysignf(r, y);
}

__device__ __forceinline__ float box_loss(
    const float* __restrict__ pred_boxes,
    const float* __restrict__ gt_corners,
    int i)
{
    const float4* cp = reinterpret_cast<const float4*>(gt_corners) + (size_t)i * 6;
    float4 q0 = cp[0], q1 = cp[1], q2 = cp[2], q3 = cp[3], q4 = cp[4], q5 = cp[5];

    int b = i >> 13;
    int m = i & (NGT - 1);
    const float* pp = pred_boxes + ((size_t)b * NPRED + m) * 7;
    float p0 = pp[0], p1v = pp[1], p2v = pp[2], p3 = pp[3];
    float p4 = pp[4], p5 = pp[5], p6 = pp[6];

    float x0=q0.x,y0=q0.y,z0=q0.z,  x1=q0.w,y1=q1.x,z1=q1.y;
    float x2=q1.z,y2=q1.w,z2=q2.x,  x3=q2.y,y3=q2.z,z3=q2.w;
    float x4=q3.x,y4=q3.y,z4=q3.z,  x5=q3.w,y5=q4.x,z5=q4.y;
    float x6=q4.z,y6=q4.w,z6=q5.x,  x7=q5.y,y7=q5.z,z7=q5.w;

    // raw moments; cov = S2 - S1*(S1/8)
    float sx=0.f, sy=0.f, sz=0.f;
    float sxx=0.f, sxy=0.f, sxz=0.f, syy=0.f, syz=0.f, szz=0.f;
#define ACC(X,Y,Z) { sx += (X); sy += (Y); sz += (Z); \
    sxx = fmaf((X),(X),sxx); sxy = fmaf((X),(Y),sxy); sxz = fmaf((X),(Z),sxz); \
    syy = fmaf((Y),(Y),syy); syz = fmaf((Y),(Z),syz); szz = fmaf((Z),(Z),szz); }
    ACC(x0,y0,z0) ACC(x1,y1,z1) ACC(x2,y2,z2) ACC(x3,y3,z3)
    ACC(x4,y4,z4) ACC(x5,y5,z5) ACC(x6,y6,z6) ACC(x7,y7,z7)
#undef ACC
    float mx = sx * 0.125f, my = sy * 0.125f, mz = sz * 0.125f;
    float axx = fmaf(-sx, mx, sxx), axy = fmaf(-sx, my, sxy);
    float axz = fmaf(-sx, mz, sxz), ayy = fmaf(-sy, my, syy);
    float ayz = fmaf(-sy, mz, syz), azz = fmaf(-sz, mz, szz);

    float qv = (axx + ayy + azz) * (1.f/3.f);
    float pp1 = axy*axy + axz*axz + ayz*ayz;
    float a0 = axx - qv, a1 = ayy - qv, a2 = azz - qv;
    float p2 = fmaxf((a0*a0 + a1*a1 + a2*a2 + 2.f*pp1) * (1.f/6.f), 1e-30f);
    float ip = rsqrtf(p2);          // shared: p = p2*ip, 1/p = ip
    float p  = p2 * ip;
    float b00=a0*ip, b11=a1*ip, b22=a2*ip;
    float b01=axy*ip, b02=axz*ip, b12=ayz*ip;
    float detb = b00*(b11*b22 - b12*b12)
               - b01*(b01*b22 - b12*b02)
               + b02*(b01*b12 - b11*b02);
    float r   = fminf(fmaxf(0.5f*detb, -1.f), 1.f);
    float phi = facos(r) * (1.f/3.f);
    float sph, cph;
    __sincosf(phi, &sph, &cph);
    // cos(phi + 2*pi/3) = -0.5*c - (sqrt(3)/2)*s
    float c2  = fmaf(-0.5f, cph, -0.86602540378f * sph);
    float lam2 = qv + 2.f*p*cph;                    // largest
    float lam0 = qv + 2.f*p*c2;                     // smallest
    float lam1 = 3.f*qv - lam0 - lam2;

    float s0 = 2.f*fsqrt_fast(fmaxf(lam1, 0.f));
    float s1 = 2.f*fsqrt_fast(fmaxf(lam2, 0.f));
    float s2 = 2.f*fsqrt_fast(fmaxf(lam0, 0.f));

    float m00 = axx - lam0, m11 = ayy - lam0, m22 = azz - lam0;
    float c0x = axy*ayz - axz*m11, c0y = axz*axy - m00*ayz;
    float c0z = m00*m11 - axy*axy;
    float c1x = axy*m22 - axz*ayz, c1y = axz*axz - m00*m22;
    float c1z = m00*ayz - axy*axz;
    float c2x = m11*m22 - ayz*ayz, c2y = ayz*axz - axy*m22;
    float c2z = axy*ayz - m11*axz;
    float n0 = c0x*c0x + c0y*c0y + c0z*c0z;
    float n1 = c1x*c1x + c1y*c1y + c1z*c1z;
    float n2 = c2x*c2x + c2y*c2y + c2z*c2z;
    float vx = c0x, vy = c0y, nb = n0;
    if (n1 > nb) { vx = c1x; vy = c1y; nb = n1; }
    if (n2 > nb) { vx = c2x; vy = c2y; }
    float yaw = fatan2(vy, vx);

    return sl1(p0, mx) + sl1(p1v, my) + sl1(p2v, mz)
         + sl1(p3, s0) + sl1(p4, s1) + sl1(p5, s2)
         + sl1(p6, yaw);
}

__device__ __forceinline__ void score_pass(
    const float* __restrict__ pred_scores, int tid, float& lg, float& sq)
{
    if (tid < NS4) {
        float4 s = reinterpret_cast<const float4*>(pred_scores)[tid];
        int n = (tid * 4) & (NPRED - 1);
        if (n < NGT) {
            float cx = fminf(fmaxf(s.x, 1e-12f), 1.f);
            float cy = fminf(fmaxf(s.y, 1e-12f), 1.f);
            float cz = fminf(fmaxf(s.z, 1e-12f), 1.f);
            float cw = fminf(fmaxf(s.w, 1e-12f), 1.f);
            lg += __logf(cx * cy) + __logf(cz * cw);
        } else {
            sq += s.x*s.x + s.y*s.y + s.z*s.z + s.w*s.w;
        }
    }
}

__global__ void __launch_bounds__(TPB, CPS) main_k(
    const float* __restrict__ pred_boxes,
    const float* __restrict__ pred_scores,
    const float* __restrict__ gt_corners,
    float* __restrict__ out)
{
    const int tid = blockIdx.x * TPB + threadIdx.x;
    const int i1  = tid + NTH;          // second box (if any)
    const bool hasB = (i1 < NBOX);

    float reg = 0.f, lg = 0.f, sq = 0.f;

    // Temporal stagger: odd warps do the (short) score pass FIRST, shifting
    // their box-load phase so DRAM sees continuous demand instead of
    // chip-wide load/compute convoys.
    if ((threadIdx.x >> 5) & 1) {
        score_pass(pred_scores, tid, lg, sq);
        reg += box_loss(pred_boxes, gt_corners, tid);
        if (hasB) reg += box_loss(pred_boxes, gt_corners, i1);
    } else {
        reg += box_loss(pred_boxes, gt_corners, tid);
        if (hasB) reg += box_loss(pred_boxes, gt_corners, i1);
        score_pass(pred_scores, tid, lg, sq);
    }

    // ---- block reduction -> per-block float partials ----
    __shared__ float shf[3][8];
    int lane = threadIdx.x & 31, wid = threadIdx.x >> 5;
    reg = warp_redf(reg); lg = warp_redf(lg); sq = warp_redf(sq);
    if (lane == 0) { shf[0][wid] = reg; shf[1][wid] = lg; shf[2][wid] = sq; }
    __syncthreads();
    if (wid == 0) {
        float a = (lane < 8) ? shf[0][lane] : 0.f;
        float b = (lane < 8) ? shf[1][lane] : 0.f;
        float c = (lane < 8) ? shf[2][lane] : 0.f;
        a = warp_redf(a); b = warp_redf(b); c = warp_redf(c);
        if (lane == 0) {
            g_part[blockIdx.x][0] = a;
            g_part[blockIdx.x][1] = b;
            g_part[blockIdx.x][2] = c;
        }
    }

    // ---- last-block final reduction (double, runs once) ----
    __shared__ bool amLast;
    __threadfence();
    if (threadIdx.x == 0)
        amLast = (atomicAdd(&g_count, 1) == GRID - 1);
    __syncthreads();

    if (amLast) {
        double a = 0.0, b = 0.0, c = 0.0;
        for (int k = threadIdx.x; k < GRID; k += TPB) {
            a += (double)g_part[k][0];
            b += (double)g_part[k][1];
            c += (double)g_part[k][2];
        }
        a = warp_redd(a); b = warp_redd(b); c = warp_redd(c);
        __shared__ double shd[3][8];
        if (lane == 0) { shd[0][wid] = a; shd[1][wid] = b; shd[2][wid] = c; }
        __syncthreads();
        if (wid == 0) {
            double ra = (lane < 8) ? shd[0][lane] : 0.0;
            double rb = (lane < 8) ? shd[1][lane] : 0.0;
            double rc = (lane < 8) ? shd[2][lane] : 0.0;
            ra = warp_redd(ra); rb = warp_redd(rb); rc = warp_redd(rc);
            if (lane == 0) {
                double regm  = ra / (double)((long long)BATCH * NGT * 7);
                double bce   = -rb / (double)((long long)BATCH * NGT);
                double extra = 0.3 * rc / (double)BATCH;
                out[0] = (float)(regm + bce + extra);
                g_count = 0;
            }
        }
    }
}

extern "C" void kernel_launch(void* const* d_in, const int* in_sizes, int n_in,
                              void* d_out, int out_size) {
    const float* pred_boxes  = (const float*)d_in[0];
    const float* pred_scores = (const float*)d_in[1];
    const float* gt_corners  = (const float*)d_in[2];

    main_k<<<GRID, TPB>>>(pred_boxes, pred_scores, gt_corners, (float*)d_out);
}